// round 13
// baseline (speedup 1.0000x reference)
#include <cuda_runtime.h>
#include <cuda_bf16.h>
#include <cstdint>
#include <cmath>

// ---------------- problem constants ----------------
#define Nn 8192
#define Mm 50

#define CTA_ROWS 64
#define GRID (Nn / CTA_ROWS)   // 128
#define THREADS 256            // warps 0-3: GEMM1 (G1); warps 4-7: GEMM2 (G2)

// weight fragment images (uint2 entries per chunk)
#define W1_U2 3072             // [h(2)][ks(6)][nt(8)][lane(32)]
#define W2_U2 2048             // [h(2)][ks2(4)][nt(8)][lane(32)]
#define W1_B  (W1_U2 * 8)      // 24576 bytes
#define W2_B  (W2_U2 * 8)      // 16384 bytes

// smem layout (bytes)
#define SM_W1  0                          // 3 slots * 24576 = 73728
#define SM_W2  73728                      // 3 slots * 16384 = 49152
#define SM_HB  122880                     // 2 bufs * 16384 = 32768 (h frags)
#define SM_XB  155648                     // 16384 (X frag handoff)
#define SM_W0  172032                     // 512 f
#define SM_B1  (SM_W0 + 2048)
#define SM_B2  (SM_B1 + 2048)
#define SM_TH  (SM_B2 + 256)
#define SMEM_BYTES (SM_TH + 256)          // 176896

// named barrier ids
#define FULLB(b)  (1 + (b))
#define EMPTYB(b) (3 + (b))
#define XFULL 5
#define XREAD 6
#define G1BAR 7
#define G2BAR 8

__device__ __align__(16) uint2 gW1f[8][W1_U2];
__device__ __align__(16) uint2 gW2f[8][W2_U2];

// ---------------- helpers ----------------
__device__ __forceinline__ float ftanh(float x) {
    float y; asm("tanh.approx.f32 %0, %1;" : "=f"(y) : "f"(x)); return y;
}
__device__ __forceinline__ void cp16(uint32_t dst, const void* src) {
    asm volatile("cp.async.cg.shared.global [%0], [%1], 16;" :: "r"(dst), "l"(src));
}
#define CP_COMMIT() asm volatile("cp.async.commit_group;" ::: "memory")
#define CP_WAIT0()  asm volatile("cp.async.wait_group 0;" ::: "memory")
#define BAR_SYNC(id, n)   asm volatile("bar.sync %0, %1;"   :: "r"(id), "r"(n) : "memory")
#define BAR_ARRIVE(id, n) asm volatile("bar.arrive %0, %1;" :: "r"(id), "r"(n) : "memory")

__device__ __forceinline__ void split_pair(float xe, float xo, uint32_t& whi, uint32_t& wlo) {
    uint32_t h;
    asm("cvt.rn.bf16x2.f32 %0, %1, %2;" : "=r"(h) : "f"(xo), "f"(xe));
    float fe = __uint_as_float(h << 16);
    float fo = __uint_as_float(h & 0xFFFF0000u);
    uint32_t lw;
    asm("cvt.rn.bf16x2.f32 %0, %1, %2;" : "=r"(lw) : "f"(xo - fo), "f"(xe - fe));
    whi = h; wlo = lw;
}

__device__ __forceinline__ void mma16816(float d[4],
    uint32_t a0, uint32_t a1, uint32_t a2, uint32_t a3, uint2 b) {
    asm volatile(
        "mma.sync.aligned.m16n8k16.row.col.f32.bf16.bf16.f32 "
        "{%0,%1,%2,%3}, {%4,%5,%6,%7}, {%8,%9}, {%0,%1,%2,%3};"
        : "+f"(d[0]), "+f"(d[1]), "+f"(d[2]), "+f"(d[3])
        : "r"(a0), "r"(a1), "r"(a2), "r"(a3), "r"(b.x), "r"(b.y));
}

// ---------------- setup: prepack weights into fragment order, bf16 hi/lo ----
__global__ void build_frags(const float* __restrict__ W1, const float* __restrict__ W2) {
    int tid = blockIdx.x * blockDim.x + threadIdx.x;
    int stride = gridDim.x * blockDim.x;

    for (int i = tid; i < 8 * W1_U2; i += stride) {
        int l  = i & 31;
        int nt = (i >> 5) & 7;
        int r8 = i >> 8;
        int ks = r8 % 6;
        int h  = (r8 / 6) & 1;
        int ch = i / W1_U2;
        int n  = ch * 64 + nt * 8 + (l >> 2);
        int k0 = ks * 16 + (l & 3) * 2;
        float v[4] = { W1[(size_t)(1 + k0) * 512 + n], W1[(size_t)(2 + k0) * 512 + n],
                       W1[(size_t)(9 + k0) * 512 + n], W1[(size_t)(10 + k0) * 512 + n] };
        uint32_t p[2];
        #pragma unroll
        for (int q = 0; q < 2; q++) {
            float a = v[2*q], bq = v[2*q + 1];
            if (h) {
                a  -= __bfloat162float(__float2bfloat16(a));
                bq -= __bfloat162float(__float2bfloat16(bq));
            }
            p[q] = (uint32_t)__bfloat16_as_ushort(__float2bfloat16(a))
                 | ((uint32_t)__bfloat16_as_ushort(__float2bfloat16(bq)) << 16);
        }
        gW1f[ch][((h * 6 + ks) * 8 + nt) * 32 + l] = make_uint2(p[0], p[1]);
    }

    for (int i = tid; i < 8 * W2_U2; i += stride) {
        int l  = i & 31;
        int nt = (i >> 5) & 7;
        int r8 = i >> 8;
        int ks = r8 % 4;
        int h  = (r8 / 4) & 1;
        int ch = i / W2_U2;
        int n  = nt * 8 + (l >> 2);
        int k0 = ch * 64 + ks * 16 + (l & 3) * 2;
        float v[4] = { W2[(size_t)k0 * 64 + n],       W2[(size_t)(k0 + 1) * 64 + n],
                       W2[(size_t)(k0 + 8) * 64 + n], W2[(size_t)(k0 + 9) * 64 + n] };
        uint32_t p[2];
        #pragma unroll
        for (int q = 0; q < 2; q++) {
            float a = v[2*q], bq = v[2*q + 1];
            if (h) {
                a  -= __bfloat162float(__float2bfloat16(a));
                bq -= __bfloat162float(__float2bfloat16(bq));
            }
            p[q] = (uint32_t)__bfloat16_as_ushort(__float2bfloat16(a))
                 | ((uint32_t)__bfloat16_as_ushort(__float2bfloat16(bq)) << 16);
        }
        gW2f[ch][((h * 4 + ks) * 8 + nt) * 32 + l] = make_uint2(p[0], p[1]);
    }
}

// ---------------- main rollout: warp-specialized producer/consumer ----------------
__global__ void __launch_bounds__(THREADS, 1) rollout_ws(
    const float* __restrict__ X0, const float* __restrict__ V0,
    const float* __restrict__ Y,  const float* __restrict__ theta,
    const float* __restrict__ W1, const float* __restrict__ b1,
    const float* __restrict__ W2, const float* __restrict__ b2,
    const float* __restrict__ noise, const int* __restrict__ obs_index,
    float* __restrict__ out)
{
    extern __shared__ __align__(16) unsigned char smem[];
    uint2* sW1 = (uint2*)(smem + SM_W1);
    uint2* sW2 = (uint2*)(smem + SM_W2);
    float* sW0 = (float*)(smem + SM_W0);
    float* sB1 = (float*)(smem + SM_B1);
    float* sB2 = (float*)(smem + SM_B2);
    float* sTH = (float*)(smem + SM_TH);
    const uint32_t sb = (uint32_t)__cvta_generic_to_shared(smem);

    const int tid = threadIdx.x;
    const int l = tid & 31;
    const int w = tid >> 5;
    const int g = l >> 2, c = l & 3;
    const int row0 = blockIdx.x * CTA_ROWS;

    const float dt = 1.0f / (float)Mm;
    const float sqdt = sqrtf(dt);
    const int obs = *obs_index;

    for (int i = tid; i < 512; i += THREADS) { sW0[i] = W1[i]; sB1[i] = b1[i]; }
    if (tid < 64) { sB2[tid] = b2[tid]; sTH[tid] = theta[tid]; }
    __syncthreads();

    if (w < 4) {
        // ================= G1: GEMM1 + tanh + split (producer) =================
        const int tile = w;
        const int rA = row0 + tile * 16 + g;
        const int rB = rA + 8;

        // X frags: initial from X0
        uint32_t Xhi[4][4], Xlo[4][4];
        #pragma unroll
        for (int ks = 0; ks < 4; ks++) {
            int k0 = ks * 16 + c * 2;
            float2 a0 = *(const float2*)(X0 + (size_t)rA * 64 + k0);
            float2 b0 = *(const float2*)(X0 + (size_t)rB * 64 + k0);
            float2 a1 = *(const float2*)(X0 + (size_t)rA * 64 + k0 + 8);
            float2 b1v = *(const float2*)(X0 + (size_t)rB * 64 + k0 + 8);
            split_pair(a0.x, a0.y, Xhi[ks][0], Xlo[ks][0]);
            split_pair(b0.x, b0.y, Xhi[ks][1], Xlo[ks][1]);
            split_pair(a1.x, a1.y, Xhi[ks][2], Xlo[ks][2]);
            split_pair(b1v.x, b1v.y, Xhi[ks][3], Xlo[ks][3]);
        }
        // Y frags (static)
        uint32_t Yhi[2][4], Ylo[2][4];
        #pragma unroll
        for (int ks = 0; ks < 2; ks++) {
            int k0 = ks * 16 + c * 2;
            float2 a0 = *(const float2*)(Y + (size_t)rA * 32 + (size_t)obs * 32 + k0);
            float2 b0 = *(const float2*)(Y + (size_t)rB * 32 + (size_t)obs * 32 + k0);
            float2 a1 = *(const float2*)(Y + (size_t)rA * 32 + (size_t)obs * 32 + k0 + 8);
            float2 b1v = *(const float2*)(Y + (size_t)rB * 32 + (size_t)obs * 32 + k0 + 8);
            split_pair(a0.x, a0.y, Yhi[ks][0], Ylo[ks][0]);
            split_pair(b0.x, b0.y, Yhi[ks][1], Ylo[ks][1]);
            split_pair(a1.x, a1.y, Yhi[ks][2], Ylo[ks][2]);
            split_pair(b1v.x, b1v.y, Yhi[ks][3], Ylo[ks][3]);
        }

        const int t1 = tid;  // 0..127
        // prime W1 slots 0,1
        #pragma unroll
        for (int s = 0; s < 2; s++) {
            const uint2* src = gW1f[s];
            uint32_t dst = sb + SM_W1 + (uint32_t)s * W1_B;
            for (int i = t1; i < W1_U2 / 2; i += 128) cp16(dst + i * 16, src + i * 2);
            CP_COMMIT();
        }

        for (int m = 0; m < Mm; m++) {
            const float s_cur = (float)m * dt;
            if (m > 0) {
                BAR_SYNC(XFULL, 256);
                #pragma unroll
                for (int ks = 0; ks < 4; ks++) {
                    uint4 hx = *(uint4*)(smem + SM_XB + (((tile * 4 + ks) * 2 + 0) * 32 + l) * 16);
                    uint4 lx = *(uint4*)(smem + SM_XB + (((tile * 4 + ks) * 2 + 1) * 32 + l) * 16);
                    Xhi[ks][0] = hx.x; Xhi[ks][1] = hx.y; Xhi[ks][2] = hx.z; Xhi[ks][3] = hx.w;
                    Xlo[ks][0] = lx.x; Xlo[ks][1] = lx.y; Xlo[ks][2] = lx.z; Xlo[ks][3] = lx.w;
                }
            }
            BAR_ARRIVE(XREAD, 256);

            for (int ch = 0; ch < 8; ch++) {
                const int gc = m * 8 + ch;
                const int b = gc & 1;
                CP_WAIT0();
                BAR_SYNC(G1BAR, 128);
                {   // prefetch W1 chunk gc+2
                    const uint2* src = gW1f[(gc + 2) & 7];
                    uint32_t dst = sb + SM_W1 + (uint32_t)((gc + 2) % 3) * W1_B;
                    for (int i = t1; i < W1_U2 / 2; i += 128) cp16(dst + i * 16, src + i * 2);
                    CP_COMMIT();
                }
                const uint2* wb = sW1 + (gc % 3) * W1_U2;

                // GEMM1: 144 MMA
                float C1[8][4];
                #pragma unroll
                for (int nt = 0; nt < 8; nt++)
                    #pragma unroll
                    for (int q = 0; q < 4; q++) C1[nt][q] = 0.0f;
                #pragma unroll
                for (int ks = 0; ks < 6; ks++) {
                    uint32_t AH[4], AL[4];
                    #pragma unroll
                    for (int q = 0; q < 4; q++) {
                        AH[q] = (ks < 4) ? Xhi[ks & 3][q] : Yhi[ks & 1][q];
                        AL[q] = (ks < 4) ? Xlo[ks & 3][q] : Ylo[ks & 1][q];
                    }
                    uint2 bh[8];
                    #pragma unroll
                    for (int nt = 0; nt < 8; nt++) bh[nt] = wb[(ks * 8 + nt) * 32 + l];
                    #pragma unroll
                    for (int nt = 0; nt < 8; nt++) mma16816(C1[nt], AH[0], AH[1], AH[2], AH[3], bh[nt]);
                    #pragma unroll
                    for (int nt = 0; nt < 8; nt++) mma16816(C1[nt], AL[0], AL[1], AL[2], AL[3], bh[nt]);
                    uint2 bl[8];
                    #pragma unroll
                    for (int nt = 0; nt < 8; nt++) bl[nt] = wb[((6 + ks) * 8 + nt) * 32 + l];
                    #pragma unroll
                    for (int nt = 0; nt < 8; nt++) mma16816(C1[nt], AH[0], AH[1], AH[2], AH[3], bl[nt]);
                }

                if (gc >= 2) BAR_SYNC(EMPTYB(b), 256);

                // tanh + split -> h frags to smem
                #pragma unroll
                for (int ks2 = 0; ks2 < 4; ks2++) {
                    int col0 = ch * 64 + ks2 * 16 + c * 2;
                    float2 w0a = *(const float2*)&sW0[col0];
                    float2 b1a = *(const float2*)&sB1[col0];
                    float2 w0b = *(const float2*)&sW0[col0 + 8];
                    float2 b1b = *(const float2*)&sB1[col0 + 8];
                    float hb0 = fmaf(s_cur, w0a.x, b1a.x), hb1 = fmaf(s_cur, w0a.y, b1a.y);
                    float hb2 = fmaf(s_cur, w0b.x, b1b.x), hb3 = fmaf(s_cur, w0b.y, b1b.y);
                    float h00 = ftanh(C1[2*ks2][0] + hb0), h01 = ftanh(C1[2*ks2][1] + hb1);
                    float h02 = ftanh(C1[2*ks2][2] + hb0), h03 = ftanh(C1[2*ks2][3] + hb1);
                    float h10 = ftanh(C1[2*ks2+1][0] + hb2), h11 = ftanh(C1[2*ks2+1][1] + hb3);
                    float h12 = ftanh(C1[2*ks2+1][2] + hb2), h13 = ftanh(C1[2*ks2+1][3] + hb3);
                    uint4 hv, lv;
                    split_pair(h00, h01, hv.x, lv.x);
                    split_pair(h02, h03, hv.y, lv.y);
                    split_pair(h10, h11, hv.z, lv.z);
                    split_pair(h12, h13, hv.w, lv.w);
                    uint32_t off = SM_HB + b * 16384 + (((tile * 4 + ks2) * 2) * 32 + l) * 16;
                    *(uint4*)(smem + off)       = hv;
                    *(uint4*)(smem + off + 512) = lv;
                }
                BAR_ARRIVE(FULLB(b), 256);
            }
        }
        CP_WAIT0();
    } else {
        // ================= G2: GEMM2 + state owner (consumer) =================
        const int tile = w - 4;
        const int rA = row0 + tile * 16 + g;
        const int rB = rA + 8;
        const int t2 = tid - 128;  // 0..127

        float X[8][4];
        #pragma unroll
        for (int j = 0; j < 8; j++) {
            int col = c * 2 + 8 * j;
            float2 va = *(const float2*)(X0 + (size_t)rA * 64 + col);
            float2 vb = *(const float2*)(X0 + (size_t)rB * 64 + col);
            X[j][0] = va.x; X[j][1] = va.y; X[j][2] = vb.x; X[j][3] = vb.y;
        }
        float vA = 0.0f, vB = 0.0f;

        // prime W2 slots 0,1
        #pragma unroll
        for (int s = 0; s < 2; s++) {
            const uint2* src = gW2f[s];
            uint32_t dst = sb + SM_W2 + (uint32_t)s * W2_B;
            for (int i = t2; i < W2_U2 / 2; i += 128) cp16(dst + i * 16, src + i * 2);
            CP_COMMIT();
        }

        for (int m = 0; m < Mm; m++) {
            float D2[8][4];
            #pragma unroll
            for (int nt = 0; nt < 8; nt++)
                #pragma unroll
                for (int q = 0; q < 4; q++) D2[nt][q] = 0.0f;

            float2 nA[8], nB[8];

            for (int ch = 0; ch < 8; ch++) {
                const int gc = m * 8 + ch;
                const int b = gc & 1;
                CP_WAIT0();
                BAR_SYNC(G2BAR, 128);
                {   // prefetch W2 chunk gc+2
                    const uint2* src = gW2f[(gc + 2) & 7];
                    uint32_t dst = sb + SM_W2 + (uint32_t)((gc + 2) % 3) * W2_B;
                    for (int i = t2; i < W2_U2 / 2; i += 128) cp16(dst + i * 16, src + i * 2);
                    CP_COMMIT();
                }
                if (ch == 7) {  // issue noise LDGs before blocking
                    #pragma unroll
                    for (int nt = 0; nt < 8; nt++) {
                        int col = c * 2 + 8 * nt;
                        nA[nt] = *(const float2*)(noise + ((size_t)m * Nn + rA) * 64 + col);
                        nB[nt] = *(const float2*)(noise + ((size_t)m * Nn + rB) * 64 + col);
                    }
                }
                BAR_SYNC(FULLB(b), 256);

                uint4 hh[4], hl[4];
                #pragma unroll
                for (int ks2 = 0; ks2 < 4; ks2++) {
                    uint32_t off = SM_HB + b * 16384 + (((tile * 4 + ks2) * 2) * 32 + l) * 16;
                    hh[ks2] = *(uint4*)(smem + off);
                    hl[ks2] = *(uint4*)(smem + off + 512);
                }
                BAR_ARRIVE(EMPTYB(b), 256);

                const uint2* wb2 = sW2 + (gc % 3) * W2_U2;
                #pragma unroll
                for (int ks2 = 0; ks2 < 4; ks2++) {
                    uint2 bh[8];
                    #pragma unroll
                    for (int nt = 0; nt < 8; nt++) bh[nt] = wb2[(ks2 * 8 + nt) * 32 + l];
                    #pragma unroll
                    for (int nt = 0; nt < 8; nt++)
                        mma16816(D2[nt], hh[ks2].x, hh[ks2].y, hh[ks2].z, hh[ks2].w, bh[nt]);
                    #pragma unroll
                    for (int nt = 0; nt < 8; nt++)
                        mma16816(D2[nt], hl[ks2].x, hl[ks2].y, hl[ks2].z, hl[ks2].w, bh[nt]);
                    uint2 bl[8];
                    #pragma unroll
                    for (int nt = 0; nt < 8; nt++) bl[nt] = wb2[((4 + ks2) * 8 + nt) * 32 + l];
                    #pragma unroll
                    for (int nt = 0; nt < 8; nt++)
                        mma16816(D2[nt], hh[ks2].x, hh[ks2].y, hh[ks2].z, hh[ks2].w, bl[nt]);
                }
            }

            // ---- step epilogue: Z -> V, X update ----
            #pragma unroll
            for (int nt = 0; nt < 8; nt++) {
                int col = c * 2 + 8 * nt;
                float2 b2v = *(const float2*)&sB2[col];
                float2 thv = *(const float2*)&sTH[col];
                float z0 = D2[nt][0] + b2v.x, z1 = D2[nt][1] + b2v.y;
                float z2 = D2[nt][2] + b2v.x, z3 = D2[nt][3] + b2v.y;
                float wa0 = sqdt * nA[nt].x, wa1 = sqdt * nA[nt].y;
                float wb0 = sqdt * nB[nt].x, wb1 = sqdt * nB[nt].y;
                vA += z0 * wa0 + z1 * wa1 - 0.5f * dt * (z0 * z0 + z1 * z1);
                vB += z2 * wb0 + z3 * wb1 - 0.5f * dt * (z2 * z2 + z3 * z3);
                X[nt][0] += dt * (thv.x - X[nt][0] - z0) + wa0;
                X[nt][1] += dt * (thv.y - X[nt][1] - z1) + wa1;
                X[nt][2] += dt * (thv.x - X[nt][2] - z2) + wb0;
                X[nt][3] += dt * (thv.y - X[nt][3] - z3) + wb1;
            }

            if (m < Mm - 1) {
                BAR_SYNC(XREAD, 256);   // G1 done reading previous X frags
                #pragma unroll
                for (int ks = 0; ks < 4; ks++) {
                    uint4 hv, lv;
                    split_pair(X[2*ks][0],   X[2*ks][1],   hv.x, lv.x);
                    split_pair(X[2*ks][2],   X[2*ks][3],   hv.y, lv.y);
                    split_pair(X[2*ks+1][0], X[2*ks+1][1], hv.z, lv.z);
                    split_pair(X[2*ks+1][2], X[2*ks+1][3], hv.w, lv.w);
                    uint32_t off = SM_XB + (((tile * 4 + ks) * 2) * 32 + l) * 16;
                    *(uint4*)(smem + off)       = hv;
                    *(uint4*)(smem + off + 512) = lv;
                }
                BAR_ARRIVE(XFULL, 256);
            } else {
                BAR_SYNC(XREAD, 256);   // balance G1's final arrive
            }
        }

        // ---- output ----
        #pragma unroll
        for (int nt = 0; nt < 8; nt++) {
            int col = c * 2 + 8 * nt;
            *(float2*)(out + (size_t)rA * 64 + col) = make_float2(X[nt][0], X[nt][1]);
            *(float2*)(out + (size_t)rB * 64 + col) = make_float2(X[nt][2], X[nt][3]);
        }
        vA += __shfl_down_sync(0xffffffffu, vA, 2, 4);
        vA += __shfl_down_sync(0xffffffffu, vA, 1, 4);
        vB += __shfl_down_sync(0xffffffffu, vB, 2, 4);
        vB += __shfl_down_sync(0xffffffffu, vB, 1, 4);
        if (c == 0) {
            out[(size_t)Nn * 64 + rA] = V0[rA] + vA;
            out[(size_t)Nn * 64 + rB] = V0[rB] + vB;
        }
        CP_WAIT0();
    }
}

extern "C" void kernel_launch(void* const* d_in, const int* in_sizes, int n_in,
                              void* d_out, int out_size)
{
    (void)in_sizes; (void)n_in; (void)out_size;
    cudaFuncSetAttribute(rollout_ws,
                         cudaFuncAttributeMaxDynamicSharedMemorySize, SMEM_BYTES);

    build_frags<<<64, 256>>>((const float*)d_in[4], (const float*)d_in[6]);
    rollout_ws<<<GRID, THREADS, SMEM_BYTES>>>(
        (const float*)d_in[0], (const float*)d_in[1], (const float*)d_in[2],
        (const float*)d_in[3], (const float*)d_in[4], (const float*)d_in[5],
        (const float*)d_in[6], (const float*)d_in[7], (const float*)d_in[8],
        (const int*)d_in[9],   (float*)d_out);
}

// round 14
// speedup vs baseline: 1.1263x; 1.1263x over previous
#include <cuda_runtime.h>
#include <cuda_bf16.h>
#include <cstdint>
#include <cmath>

// ---------------- problem constants ----------------
#define Nn 8192
#define Mm 50

#define CTA_ROWS 32
#define GRID (Nn / CTA_ROWS)   // 256  -> 2 CTAs per SM (independent, free-drifting)
#define THREADS 128            // 4 warps: (rowhalf, nhalf) = (w&1, w>>1)

// weight fragment image: per chunk, uint2 entries
//   W1: [h(2)][ks(6)][nt(8)][lane(32)]  -> 3072 uint2
//   W2: [h(2)][ks2(4)][nt(8)][lane(32)] -> 2048 uint2, at offset 3072
#define WCH_U2 5120
#define W2_OFF 3072
#define WCH_B  (WCH_U2 * 8)    // 40960 bytes per chunk

// smem layout (bytes) — must fit 2 CTAs/SM
#define SM_W   0                          // 2 slots * 40960 = 81920
#define SM_EX  81920                      // 128 thr * 33 f * 4 = 16896 (D2 exchange)
#define SM_W0  98816                      // 512 f
#define SM_B1  (SM_W0 + 2048)
#define SM_B2  (SM_B1 + 2048)
#define SM_TH  (SM_B2 + 256)
#define SMEM_BYTES (SM_TH + 256)          // 103424  (x2 = 206848 < 227KB)

__device__ __align__(16) uint2 gWf[8][WCH_U2];

// ---------------- helpers ----------------
__device__ __forceinline__ float ftanh(float x) {
    float y; asm("tanh.approx.f32 %0, %1;" : "=f"(y) : "f"(x)); return y;
}
__device__ __forceinline__ void cp16(uint32_t dst, const void* src) {
    asm volatile("cp.async.cg.shared.global [%0], [%1], 16;" :: "r"(dst), "l"(src));
}
#define CP_COMMIT() asm volatile("cp.async.commit_group;" ::: "memory")
#define CP_WAIT0()  asm volatile("cp.async.wait_group 0;" ::: "memory")

// split two fp32 (xe = even-k, xo = odd-k) into bf16x2 hi and lo words, even in low half
__device__ __forceinline__ void split_pair(float xe, float xo, uint32_t& whi, uint32_t& wlo) {
    uint32_t h;
    asm("cvt.rn.bf16x2.f32 %0, %1, %2;" : "=r"(h) : "f"(xo), "f"(xe));
    float fe = __uint_as_float(h << 16);
    float fo = __uint_as_float(h & 0xFFFF0000u);
    uint32_t lw;
    asm("cvt.rn.bf16x2.f32 %0, %1, %2;" : "=r"(lw) : "f"(xo - fo), "f"(xe - fe));
    whi = h; wlo = lw;
}

__device__ __forceinline__ void mma16816(float d[4],
    uint32_t a0, uint32_t a1, uint32_t a2, uint32_t a3, uint2 b) {
    asm volatile(
        "mma.sync.aligned.m16n8k16.row.col.f32.bf16.bf16.f32 "
        "{%0,%1,%2,%3}, {%4,%5,%6,%7}, {%8,%9}, {%0,%1,%2,%3};"
        : "+f"(d[0]), "+f"(d[1]), "+f"(d[2]), "+f"(d[3])
        : "r"(a0), "r"(a1), "r"(a2), "r"(a3), "r"(b.x), "r"(b.y));
}

// ---------------- setup: prepack weights into B-fragment order, bf16 hi/lo ----
__global__ void build_frags(const float* __restrict__ W1, const float* __restrict__ W2) {
    int tid = blockIdx.x * blockDim.x + threadIdx.x;
    int stride = gridDim.x * blockDim.x;

    for (int i = tid; i < 24576; i += stride) {
        int l  = i & 31;
        int nt = (i >> 5) & 7;
        int r8 = i >> 8;
        int ks = r8 % 6;
        int h  = (r8 / 6) & 1;
        int ch = i / 3072;
        int n  = ch * 64 + nt * 8 + (l >> 2);
        int k0 = ks * 16 + (l & 3) * 2;
        float v[4] = { W1[(size_t)(1 + k0) * 512 + n], W1[(size_t)(2 + k0) * 512 + n],
                       W1[(size_t)(9 + k0) * 512 + n], W1[(size_t)(10 + k0) * 512 + n] };
        uint32_t p[2];
        #pragma unroll
        for (int q = 0; q < 2; q++) {
            float a = v[2*q], bq = v[2*q + 1];
            if (h) {
                a  -= __bfloat162float(__float2bfloat16(a));
                bq -= __bfloat162float(__float2bfloat16(bq));
            }
            p[q] = (uint32_t)__bfloat16_as_ushort(__float2bfloat16(a))
                 | ((uint32_t)__bfloat16_as_ushort(__float2bfloat16(bq)) << 16);
        }
        gWf[ch][((h * 6 + ks) * 8 + nt) * 32 + l] = make_uint2(p[0], p[1]);
    }

    for (int i = tid; i < 16384; i += stride) {
        int l  = i & 31;
        int nt = (i >> 5) & 7;
        int r8 = i >> 8;
        int ks = r8 % 4;
        int h  = (r8 / 4) & 1;
        int ch = i / 2048;
        int n  = nt * 8 + (l >> 2);
        int k0 = ch * 64 + ks * 16 + (l & 3) * 2;
        float v[4] = { W2[(size_t)k0 * 64 + n],       W2[(size_t)(k0 + 1) * 64 + n],
                       W2[(size_t)(k0 + 8) * 64 + n], W2[(size_t)(k0 + 9) * 64 + n] };
        uint32_t p[2];
        #pragma unroll
        for (int q = 0; q < 2; q++) {
            float a = v[2*q], bq = v[2*q + 1];
            if (h) {
                a  -= __bfloat162float(__float2bfloat16(a));
                bq -= __bfloat162float(__float2bfloat16(bq));
            }
            p[q] = (uint32_t)__bfloat16_as_ushort(__float2bfloat16(a))
                 | ((uint32_t)__bfloat16_as_ushort(__float2bfloat16(bq)) << 16);
        }
        gWf[ch][W2_OFF + ((h * 4 + ks) * 8 + nt) * 32 + l] = make_uint2(p[0], p[1]);
    }
}

// ---------------- main rollout: 32-row CTAs, N-split warps, 2 CTAs/SM ----------------
__global__ void __launch_bounds__(THREADS, 2) rollout_mma(
    const float* __restrict__ X0, const float* __restrict__ V0,
    const float* __restrict__ Y,  const float* __restrict__ theta,
    const float* __restrict__ W1, const float* __restrict__ b1,
    const float* __restrict__ W2, const float* __restrict__ b2,
    const float* __restrict__ noise, const int* __restrict__ obs_index,
    float* __restrict__ out)
{
    extern __shared__ __align__(16) unsigned char smem[];
    uint2* sW  = (uint2*)(smem + SM_W);
    float* sEX = (float*)(smem + SM_EX);
    float* sW0 = (float*)(smem + SM_W0);
    float* sB1 = (float*)(smem + SM_B1);
    float* sB2 = (float*)(smem + SM_B2);
    float* sTH = (float*)(smem + SM_TH);
    const uint32_t sb = (uint32_t)__cvta_generic_to_shared(smem);

    const int tid = threadIdx.x;
    const int l = tid & 31;
    const int w = tid >> 5;
    const int rw = w & 1;          // row half (rows rw*16 .. rw*16+15)
    const int nh = w >> 1;         // N half of GEMM1 / K half of GEMM2
    const int g = l >> 2, c = l & 3;
    const int row0 = blockIdx.x * CTA_ROWS;
    const int rA = row0 + rw * 16 + g;
    const int rB = rA + 8;

    const float dt = 1.0f / (float)Mm;
    const float sqdt = sqrtf(dt);
    const int obs = *obs_index;

    for (int i = tid; i < 512; i += THREADS) { sW0[i] = W1[i]; sB1[i] = b1[i]; }
    if (tid < 64) { sB2[tid] = b2[tid]; sTH[tid] = theta[tid]; }

    // X fp32 state (duplicated across the two N-half warps of a row pair)
    float X[8][4];
    #pragma unroll
    for (int j = 0; j < 8; j++) {
        int col = c * 2 + 8 * j;
        float2 va = *(const float2*)(X0 + (size_t)rA * 64 + col);
        float2 vb = *(const float2*)(X0 + (size_t)rB * 64 + col);
        X[j][0] = va.x; X[j][1] = va.y; X[j][2] = vb.x; X[j][3] = vb.y;
    }

    // Y A-fragments (static): GEMM1 k-steps 4,5
    uint32_t Yhi[2][4], Ylo[2][4];
    #pragma unroll
    for (int ks = 0; ks < 2; ks++)
        #pragma unroll
        for (int r = 0; r < 2; r++) {
            int yc = ks * 16 + c * 2 + r * 8;
            float2 ya = *(const float2*)(Y + (size_t)rA * 32 + (size_t)obs * 32 + yc);
            float2 yb = *(const float2*)(Y + (size_t)rB * 32 + (size_t)obs * 32 + yc);
            split_pair(ya.x, ya.y, Yhi[ks][2*r],     Ylo[ks][2*r]);
            split_pair(yb.x, yb.y, Yhi[ks][2*r + 1], Ylo[ks][2*r + 1]);
        }

    uint32_t Xhi[4][4], Xlo[4][4];
    auto build_xfrags = [&]() {
        #pragma unroll
        for (int ks = 0; ks < 4; ks++) {
            split_pair(X[2*ks][0],     X[2*ks][1],     Xhi[ks][0], Xlo[ks][0]);
            split_pair(X[2*ks][2],     X[2*ks][3],     Xhi[ks][1], Xlo[ks][1]);
            split_pair(X[2*ks + 1][0], X[2*ks + 1][1], Xhi[ks][2], Xlo[ks][2]);
            split_pair(X[2*ks + 1][2], X[2*ks + 1][3], Xhi[ks][3], Xlo[ks][3]);
        }
    };
    build_xfrags();

    float vA = 0.0f, vB = 0.0f;

    __syncthreads();   // consts staged

    // prime: chunk 0 -> slot 0
    {
        const uint2* src = gWf[0];
        for (int i = tid; i < WCH_U2 / 2; i += THREADS)
            cp16(sb + SM_W + i * 16, src + i * 2);
        CP_COMMIT();
    }

    for (int m = 0; m < Mm; m++) {
        const float s = (float)m * dt;
        float D2[8][4];
        #pragma unroll
        for (int nt = 0; nt < 8; nt++)
            #pragma unroll
            for (int i = 0; i < 4; i++) D2[nt][i] = 0.0f;

        float2 nA[8], nB[8];

        for (int ch = 0; ch < 8; ch++) {
            const int gc = m * 8 + ch;
            CP_WAIT0();
            __syncthreads();              // slot (gc&1) loaded; all warps past chunk gc-1

            // prefetch next chunk into the other slot (after barrier: no race)
            {
                const uint2* src = gWf[(ch + 1) & 7];
                uint32_t dst = sb + SM_W + (((gc + 1) & 1) ? (uint32_t)WCH_B : 0u);
                for (int i = tid; i < WCH_U2 / 2; i += THREADS)
                    cp16(dst + i * 16, src + i * 2);
                CP_COMMIT();
            }
            if (ch == 7) {  // issue noise LDGs; latency hidden behind chunk 7 compute
                #pragma unroll
                for (int nt = 0; nt < 8; nt++) {
                    int col = c * 2 + 8 * nt;
                    nA[nt] = *(const float2*)(noise + ((size_t)m * Nn + rA) * 64 + col);
                    nB[nt] = *(const float2*)(noise + ((size_t)m * Nn + rB) * 64 + col);
                }
            }

            const uint2* wb = sW + (gc & 1) * WCH_U2;

            // ---- GEMM1: C1[16 x 32] = [X|Y] @ W1chunk (this warp's N-half) ----
            float C1[4][4];
            #pragma unroll
            for (int nt = 0; nt < 4; nt++)
                #pragma unroll
                for (int q = 0; q < 4; q++) C1[nt][q] = 0.0f;

            #pragma unroll
            for (int ks = 0; ks < 6; ks++) {
                uint32_t AH[4], AL[4];
                #pragma unroll
                for (int q = 0; q < 4; q++) {
                    AH[q] = (ks < 4) ? Xhi[ks & 3][q] : Yhi[ks & 1][q];
                    AL[q] = (ks < 4) ? Xlo[ks & 3][q] : Ylo[ks & 1][q];
                }
                uint2 bh[4];
                #pragma unroll
                for (int nt = 0; nt < 4; nt++) bh[nt] = wb[(ks * 8 + nh * 4 + nt) * 32 + l];
                #pragma unroll
                for (int nt = 0; nt < 4; nt++) mma16816(C1[nt], AH[0], AH[1], AH[2], AH[3], bh[nt]);
                #pragma unroll
                for (int nt = 0; nt < 4; nt++) mma16816(C1[nt], AL[0], AL[1], AL[2], AL[3], bh[nt]);
                uint2 bl[4];
                #pragma unroll
                for (int nt = 0; nt < 4; nt++) bl[nt] = wb[((6 + ks) * 8 + nh * 4 + nt) * 32 + l];
                #pragma unroll
                for (int nt = 0; nt < 4; nt++) mma16816(C1[nt], AH[0], AH[1], AH[2], AH[3], bl[nt]);
            }

            // ---- bias + tanh + split -> GEMM2 over this warp's K-half ----
            #pragma unroll
            for (int ks2l = 0; ks2l < 2; ks2l++) {
                int col0 = ch * 64 + nh * 32 + ks2l * 16 + c * 2;
                float2 w0a = *(const float2*)&sW0[col0];
                float2 b1a = *(const float2*)&sB1[col0];
                float2 w0b = *(const float2*)&sW0[col0 + 8];
                float2 b1b = *(const float2*)&sB1[col0 + 8];
                float hb0 = fmaf(s, w0a.x, b1a.x), hb1 = fmaf(s, w0a.y, b1a.y);
                float hb2 = fmaf(s, w0b.x, b1b.x), hb3 = fmaf(s, w0b.y, b1b.y);
                float h00 = ftanh(C1[2*ks2l][0] + hb0), h01 = ftanh(C1[2*ks2l][1] + hb1);
                float h02 = ftanh(C1[2*ks2l][2] + hb0), h03 = ftanh(C1[2*ks2l][3] + hb1);
                float h10 = ftanh(C1[2*ks2l+1][0] + hb2), h11 = ftanh(C1[2*ks2l+1][1] + hb3);
                float h12 = ftanh(C1[2*ks2l+1][2] + hb2), h13 = ftanh(C1[2*ks2l+1][3] + hb3);
                uint32_t ah0, ah1, ah2, ah3, al0, al1, al2, al3;
                split_pair(h00, h01, ah0, al0);
                split_pair(h02, h03, ah1, al1);
                split_pair(h10, h11, ah2, al2);
                split_pair(h12, h13, ah3, al3);

                const int ks2 = nh * 2 + ks2l;
                uint2 bh[8];
                #pragma unroll
                for (int nt = 0; nt < 8; nt++) bh[nt] = wb[W2_OFF + (ks2 * 8 + nt) * 32 + l];
                #pragma unroll
                for (int nt = 0; nt < 8; nt++) mma16816(D2[nt], ah0, ah1, ah2, ah3, bh[nt]);
                #pragma unroll
                for (int nt = 0; nt < 8; nt++) mma16816(D2[nt], al0, al1, al2, al3, bh[nt]);
                uint2 bl[8];
                #pragma unroll
                for (int nt = 0; nt < 8; nt++) bl[nt] = wb[W2_OFF + ((4 + ks2) * 8 + nt) * 32 + l];
                #pragma unroll
                for (int nt = 0; nt < 8; nt++) mma16816(D2[nt], ah0, ah1, ah2, ah3, bl[nt]);
            }
        }

        // ---- D2 partial exchange between N-half partner warps (w ^ 2) ----
        {
            float* exw = sEX + tid * 33;
            #pragma unroll
            for (int nt = 0; nt < 8; nt++)
                #pragma unroll
                for (int q = 0; q < 4; q++) exw[nt * 4 + q] = D2[nt][q];
        }
        __syncthreads();
        {
            const float* exr = sEX + (tid ^ 64) * 33;
            #pragma unroll
            for (int nt = 0; nt < 8; nt++)
                #pragma unroll
                for (int q = 0; q < 4; q++) D2[nt][q] += exr[nt * 4 + q];
        }
        // (no second sync: sEX is next written only after next step's chunk barriers)

        // ---- step epilogue: Z -> V, X update (duplicated in partner warps) ----
        #pragma unroll
        for (int nt = 0; nt < 8; nt++) {
            int col = c * 2 + 8 * nt;
            float2 b2v = *(const float2*)&sB2[col];
            float2 thv = *(const float2*)&sTH[col];
            float z0 = D2[nt][0] + b2v.x, z1 = D2[nt][1] + b2v.y;
            float z2 = D2[nt][2] + b2v.x, z3 = D2[nt][3] + b2v.y;
            float wa0 = sqdt * nA[nt].x, wa1 = sqdt * nA[nt].y;
            float wb0 = sqdt * nB[nt].x, wb1 = sqdt * nB[nt].y;
            vA += z0 * wa0 + z1 * wa1 - 0.5f * dt * (z0 * z0 + z1 * z1);
            vB += z2 * wb0 + z3 * wb1 - 0.5f * dt * (z2 * z2 + z3 * z3);
            X[nt][0] += dt * (thv.x - X[nt][0] - z0) + wa0;
            X[nt][1] += dt * (thv.y - X[nt][1] - z1) + wa1;
            X[nt][2] += dt * (thv.x - X[nt][2] - z2) + wb0;
            X[nt][3] += dt * (thv.y - X[nt][3] - z3) + wb1;
        }
        build_xfrags();
    }

    // ---- output (N-half 0 warps cover all rows) ----
    if (nh == 0) {
        #pragma unroll
        for (int nt = 0; nt < 8; nt++) {
            int col = c * 2 + 8 * nt;
            *(float2*)(out + (size_t)rA * 64 + col) = make_float2(X[nt][0], X[nt][1]);
            *(float2*)(out + (size_t)rB * 64 + col) = make_float2(X[nt][2], X[nt][3]);
        }
        vA += __shfl_down_sync(0xffffffffu, vA, 2, 4);
        vA += __shfl_down_sync(0xffffffffu, vA, 1, 4);
        vB += __shfl_down_sync(0xffffffffu, vB, 2, 4);
        vB += __shfl_down_sync(0xffffffffu, vB, 1, 4);
        if (c == 0) {
            out[(size_t)Nn * 64 + rA] = V0[rA] + vA;
            out[(size_t)Nn * 64 + rB] = V0[rB] + vB;
        }
    }
    CP_WAIT0();     // drain trailing prefetch before exit
}

extern "C" void kernel_launch(void* const* d_in, const int* in_sizes, int n_in,
                              void* d_out, int out_size)
{
    (void)in_sizes; (void)n_in; (void)out_size;
    cudaFuncSetAttribute(rollout_mma,
                         cudaFuncAttributeMaxDynamicSharedMemorySize, SMEM_BYTES);

    build_frags<<<64, 256>>>((const float*)d_in[4], (const float*)d_in[6]);
    rollout_mma<<<GRID, THREADS, SMEM_BYTES>>>(
        (const float*)d_in[0], (const float*)d_in[1], (const float*)d_in[2],
        (const float*)d_in[3], (const float*)d_in[4], (const float*)d_in[5],
        (const float*)d_in[6], (const float*)d_in[7], (const float*)d_in[8],
        (const int*)d_in[9],   (float*)d_out);
}

// round 15
// speedup vs baseline: 1.5925x; 1.4139x over previous
#include <cuda_runtime.h>
#include <cuda_fp16.h>
#include <cstdint>
#include <cmath>

// ---------------- problem constants ----------------
#define Nn 8192
#define Mm 50

#define CTA_ROWS 64
#define GRID (Nn / CTA_ROWS)   // 128
#define THREADS 128            // 4 warps, each owns 16 rows

// weight fragment image: per chunk, uint2 entries (fp16 hi/lo of W)
//   W1: [h(2)][ks(6)][nt(8)][lane(32)]  -> 3072 uint2
//   W2: [h(2)][ks2(4)][nt(8)][lane(32)] -> 2048 uint2, at offset 3072
#define WCH_U2 5120
#define W2_OFF 3072
#define WCH_B  (WCH_U2 * 8)    // 40960 bytes per chunk

// smem layout (bytes)
#define NZ_STRIDE 68                      // floats; 272 B ≡ 0 (mod 16): cp.async-safe
#define NZ_BUF (64 * NZ_STRIDE * 4)       // 17408
#define SM_W   0                          // 2 * 40960 = 81920
#define SM_NZ  81920                      // 2 * 17408 = 34816
#define SM_W0  (SM_NZ + 2 * NZ_BUF)       // 116736
#define SM_B1  (SM_W0 + 2048)
#define SM_B2  (SM_B1 + 2048)
#define SM_TH  (SM_B2 + 256)
#define SMEM_BYTES (SM_TH + 256)          // 121344

__device__ __align__(16) uint2 gWf[8][WCH_U2];

// ---------------- helpers ----------------
__device__ __forceinline__ float ftanh(float x) {
    float y; asm("tanh.approx.f32 %0, %1;" : "=f"(y) : "f"(x)); return y;
}
__device__ __forceinline__ void cp16(uint32_t dst, const void* src) {
    asm volatile("cp.async.cg.shared.global [%0], [%1], 16;" :: "r"(dst), "l"(src));
}
#define CP_COMMIT() asm volatile("cp.async.commit_group;" ::: "memory")
#define CP_WAIT0()  asm volatile("cp.async.wait_group 0;" ::: "memory")

// pack two fp32 (xe = even-k, xo = odd-k) into one f16x2 word, even in low half
__device__ __forceinline__ uint32_t pack_pair(float xe, float xo) {
    uint32_t h;
    asm("cvt.rn.f16x2.f32 %0, %1, %2;" : "=r"(h) : "f"(xo), "f"(xe));
    return h;
}

__device__ __forceinline__ void mma16816(float d[4],
    uint32_t a0, uint32_t a1, uint32_t a2, uint32_t a3, uint2 b) {
    asm volatile(
        "mma.sync.aligned.m16n8k16.row.col.f32.f16.f16.f32 "
        "{%0,%1,%2,%3}, {%4,%5,%6,%7}, {%8,%9}, {%0,%1,%2,%3};"
        : "+f"(d[0]), "+f"(d[1]), "+f"(d[2]), "+f"(d[3])
        : "r"(a0), "r"(a1), "r"(a2), "r"(a3), "r"(b.x), "r"(b.y));
}

// ---------------- setup: prepack weights into B-fragment order, fp16 hi/lo ----
__global__ void build_frags(const float* __restrict__ W1, const float* __restrict__ W2) {
    int tid = blockIdx.x * blockDim.x + threadIdx.x;
    int stride = gridDim.x * blockDim.x;

    // W1 frags: 8ch x 2h x 6ks x 8nt x 32l = 24576 uint2
    for (int i = tid; i < 24576; i += stride) {
        int l  = i & 31;
        int nt = (i >> 5) & 7;
        int r8 = i >> 8;
        int ks = r8 % 6;
        int h  = (r8 / 6) & 1;
        int ch = i / 3072;
        int n  = ch * 64 + nt * 8 + (l >> 2);
        int k0 = ks * 16 + (l & 3) * 2;
        float v[4] = { W1[(size_t)(1 + k0) * 512 + n], W1[(size_t)(2 + k0) * 512 + n],
                       W1[(size_t)(9 + k0) * 512 + n], W1[(size_t)(10 + k0) * 512 + n] };
        uint32_t p[2];
        #pragma unroll
        for (int q = 0; q < 2; q++) {
            float a = v[2*q], bq = v[2*q + 1];
            if (h) {
                a  -= __half2float(__float2half(a));
                bq -= __half2float(__float2half(bq));
            }
            p[q] = (uint32_t)__half_as_ushort(__float2half(a))
                 | ((uint32_t)__half_as_ushort(__float2half(bq)) << 16);
        }
        gWf[ch][((h * 6 + ks) * 8 + nt) * 32 + l] = make_uint2(p[0], p[1]);
    }

    // W2 frags: 8ch x 2h x 4ks x 8nt x 32l = 16384 uint2
    for (int i = tid; i < 16384; i += stride) {
        int l  = i & 31;
        int nt = (i >> 5) & 7;
        int r8 = i >> 8;
        int ks = r8 % 4;
        int h  = (r8 / 4) & 1;
        int ch = i / 2048;
        int n  = nt * 8 + (l >> 2);
        int k0 = ch * 64 + ks * 16 + (l & 3) * 2;
        float v[4] = { W2[(size_t)k0 * 64 + n],       W2[(size_t)(k0 + 1) * 64 + n],
                       W2[(size_t)(k0 + 8) * 64 + n], W2[(size_t)(k0 + 9) * 64 + n] };
        uint32_t p[2];
        #pragma unroll
        for (int q = 0; q < 2; q++) {
            float a = v[2*q], bq = v[2*q + 1];
            if (h) {
                a  -= __half2float(__float2half(a));
                bq -= __half2float(__float2half(bq));
            }
            p[q] = (uint32_t)__half_as_ushort(__float2half(a))
                 | ((uint32_t)__half_as_ushort(__float2half(bq)) << 16);
        }
        gWf[ch][W2_OFF + ((h * 4 + ks) * 8 + nt) * 32 + l] = make_uint2(p[0], p[1]);
    }
}

// ---------------- main rollout: fp16 MMA, weights split hi/lo (2-term) ----------------
__global__ void __launch_bounds__(THREADS, 1) rollout_mma(
    const float* __restrict__ X0, const float* __restrict__ V0,
    const float* __restrict__ Y,  const float* __restrict__ theta,
    const float* __restrict__ W1, const float* __restrict__ b1,
    const float* __restrict__ W2, const float* __restrict__ b2,
    const float* __restrict__ noise, const int* __restrict__ obs_index,
    float* __restrict__ out)
{
    extern __shared__ __align__(16) unsigned char smem[];
    uint2* sW  = (uint2*)(smem + SM_W);
    float* sNZ = (float*)(smem + SM_NZ);
    float* sW0 = (float*)(smem + SM_W0);
    float* sB1 = (float*)(smem + SM_B1);
    float* sB2 = (float*)(smem + SM_B2);
    float* sTH = (float*)(smem + SM_TH);
    const uint32_t sb = (uint32_t)__cvta_generic_to_shared(smem);

    const int tid = threadIdx.x;
    const int w = tid >> 5, l = tid & 31;
    const int g = l >> 2, c = l & 3;
    const int row0 = blockIdx.x * CTA_ROWS;
    const int rA = row0 + w * 16 + g;       // fragment row (groupID)
    const int rB = rA + 8;                  // fragment row (groupID+8)

    const float dt = 1.0f / (float)Mm;
    const float sqdt = sqrtf(dt);
    const int obs = *obs_index;

    for (int i = tid; i < 512; i += THREADS) { sW0[i] = W1[i]; sB1[i] = b1[i]; }
    if (tid < 64) { sB2[tid] = b2[tid]; sTH[tid] = theta[tid]; }

    // X fp32 state, fragment-distributed: X[j] = {(rA,2c+8j),(rA,+1),(rB,2c+8j),(rB,+1)}
    float X[8][4];
    #pragma unroll
    for (int j = 0; j < 8; j++) {
        int col = c * 2 + 8 * j;
        float2 va = *(const float2*)(X0 + (size_t)rA * 64 + col);
        float2 vb = *(const float2*)(X0 + (size_t)rB * 64 + col);
        X[j][0] = va.x; X[j][1] = va.y; X[j][2] = vb.x; X[j][3] = vb.y;
    }

    // Y A-fragments (static, single fp16): GEMM1 k-steps 4,5
    uint32_t Yf[2][4];
    #pragma unroll
    for (int ks = 0; ks < 2; ks++)
        #pragma unroll
        for (int r = 0; r < 2; r++) {
            int yc = ks * 16 + c * 2 + r * 8;
            float2 ya = *(const float2*)(Y + (size_t)rA * 32 + (size_t)obs * 32 + yc);
            float2 yb = *(const float2*)(Y + (size_t)rB * 32 + (size_t)obs * 32 + yc);
            Yf[ks][2*r]     = pack_pair(ya.x, ya.y);
            Yf[ks][2*r + 1] = pack_pair(yb.x, yb.y);
        }

    // X A-fragments (rebuilt per step, single fp16)
    uint32_t Xf[4][4];
    auto build_xfrags = [&]() {
        #pragma unroll
        for (int ks = 0; ks < 4; ks++) {
            Xf[ks][0] = pack_pair(X[2*ks][0],     X[2*ks][1]);
            Xf[ks][1] = pack_pair(X[2*ks][2],     X[2*ks][3]);
            Xf[ks][2] = pack_pair(X[2*ks + 1][0], X[2*ks + 1][1]);
            Xf[ks][3] = pack_pair(X[2*ks + 1][2], X[2*ks + 1][3]);
        }
    };
    build_xfrags();

    float vA = 0.0f, vB = 0.0f;

    // prime: chunk 0 weights + step 0 noise
    {
        const uint2* src = gWf[0];
        for (int i = tid; i < WCH_U2 / 2; i += THREADS)
            cp16(sb + SM_W + i * 16, src + i * 2);
        const float* nb = noise + (size_t)row0 * 64;
        for (int i = tid; i < 1024; i += THREADS) {
            int r = i >> 4, jj = i & 15;
            cp16(sb + SM_NZ + r * (NZ_STRIDE * 4) + jj * 16, nb + (size_t)r * 64 + jj * 4);
        }
        CP_COMMIT();
    }

    for (int m = 0; m < Mm; m++) {
        const float s = (float)m * dt;
        float D2[8][4];
        #pragma unroll
        for (int nt = 0; nt < 8; nt++)
            #pragma unroll
            for (int i = 0; i < 4; i++) D2[nt][i] = 0.0f;

        for (int ch = 0; ch < 8; ch++) {
            const int gc = m * 8 + ch;
            CP_WAIT0();
            __syncthreads();              // weights(gc) visible; all warps done with gc-1

            // prefetch next chunk weights (issued AFTER barrier: no buffer race)
            {
                const uint2* src = gWf[(ch + 1) & 7];
                uint32_t dst = sb + SM_W + (((gc + 1) & 1) ? (uint32_t)WCH_B : 0u);
                for (int i = tid; i < WCH_U2 / 2; i += THREADS)
                    cp16(dst + i * 16, src + i * 2);
                CP_COMMIT();
            }
            if (ch == 4 && m + 1 < Mm) {   // stage next step's noise mid-step
                const float* nb = noise + ((size_t)(m + 1) * Nn + (size_t)row0) * 64;
                uint32_t nzd = sb + SM_NZ + (((m + 1) & 1) ? (uint32_t)NZ_BUF : 0u);
                for (int i = tid; i < 1024; i += THREADS) {
                    int r = i >> 4, jj = i & 15;
                    cp16(nzd + r * (NZ_STRIDE * 4) + jj * 16, nb + (size_t)r * 64 + jj * 4);
                }
                CP_COMMIT();
            }

            const uint2* wb = sW + (gc & 1) * WCH_U2;

            // ---- GEMM1: C1[16x64] = [X|Y] @ (W1hi + W1lo), 2 terms ----
            float C1[8][4];
            #pragma unroll
            for (int nt = 0; nt < 8; nt++)
                #pragma unroll
                for (int i = 0; i < 4; i++) C1[nt][i] = 0.0f;

            #pragma unroll
            for (int ks = 0; ks < 6; ks++) {
                uint32_t A0, A1, A2, A3;
                if (ks < 4) { A0 = Xf[ks][0]; A1 = Xf[ks][1]; A2 = Xf[ks][2]; A3 = Xf[ks][3]; }
                else        { A0 = Yf[ks-4][0]; A1 = Yf[ks-4][1]; A2 = Yf[ks-4][2]; A3 = Yf[ks-4][3]; }
                uint2 bh[8];
                #pragma unroll
                for (int nt = 0; nt < 8; nt++) bh[nt] = wb[(ks * 8 + nt) * 32 + l];
                #pragma unroll
                for (int nt = 0; nt < 8; nt++) mma16816(C1[nt], A0, A1, A2, A3, bh[nt]);
                uint2 bl[8];
                #pragma unroll
                for (int nt = 0; nt < 8; nt++) bl[nt] = wb[((6 + ks) * 8 + nt) * 32 + l];
                #pragma unroll
                for (int nt = 0; nt < 8; nt++) mma16816(C1[nt], A0, A1, A2, A3, bl[nt]);
            }

            // ---- bias + tanh + fp16 pack -> GEMM2 (C1 frags become A frags) ----
            const int cbase = ch * 64;
            #pragma unroll
            for (int ks2 = 0; ks2 < 4; ks2++) {
                int col0 = cbase + ks2 * 16 + c * 2;
                float2 w0a = *(const float2*)&sW0[col0];
                float2 b1a = *(const float2*)&sB1[col0];
                float2 w0b = *(const float2*)&sW0[col0 + 8];
                float2 b1b = *(const float2*)&sB1[col0 + 8];
                float hb0 = fmaf(s, w0a.x, b1a.x), hb1 = fmaf(s, w0a.y, b1a.y);
                float hb2 = fmaf(s, w0b.x, b1b.x), hb3 = fmaf(s, w0b.y, b1b.y);
                uint32_t a0 = pack_pair(ftanh(C1[2*ks2][0] + hb0), ftanh(C1[2*ks2][1] + hb1));
                uint32_t a1 = pack_pair(ftanh(C1[2*ks2][2] + hb0), ftanh(C1[2*ks2][3] + hb1));
                uint32_t a2 = pack_pair(ftanh(C1[2*ks2+1][0] + hb2), ftanh(C1[2*ks2+1][1] + hb3));
                uint32_t a3 = pack_pair(ftanh(C1[2*ks2+1][2] + hb2), ftanh(C1[2*ks2+1][3] + hb3));

                uint2 bh[8];
                #pragma unroll
                for (int nt = 0; nt < 8; nt++) bh[nt] = wb[W2_OFF + (ks2 * 8 + nt) * 32 + l];
                #pragma unroll
                for (int nt = 0; nt < 8; nt++) mma16816(D2[nt], a0, a1, a2, a3, bh[nt]);
                uint2 bl[8];
                #pragma unroll
                for (int nt = 0; nt < 8; nt++) bl[nt] = wb[W2_OFF + ((4 + ks2) * 8 + nt) * 32 + l];
                #pragma unroll
                for (int nt = 0; nt < 8; nt++) mma16816(D2[nt], a0, a1, a2, a3, bl[nt]);
            }
        }

        // ---- step epilogue: Z -> V, X update (all register/fragment local) ----
        const float* nzb = sNZ + (m & 1) * (NZ_BUF / 4) + (w * 16 + g) * NZ_STRIDE + c * 2;
        #pragma unroll
        for (int nt = 0; nt < 8; nt++) {
            int col = c * 2 + 8 * nt;
            float2 b2v = *(const float2*)&sB2[col];
            float2 thv = *(const float2*)&sTH[col];
            float2 na  = *(const float2*)(nzb + 8 * nt);
            float2 nb2 = *(const float2*)(nzb + 8 * NZ_STRIDE + 8 * nt);
            float z0 = D2[nt][0] + b2v.x, z1 = D2[nt][1] + b2v.y;
            float z2 = D2[nt][2] + b2v.x, z3 = D2[nt][3] + b2v.y;
            float wa0 = sqdt * na.x,  wa1 = sqdt * na.y;
            float wb0 = sqdt * nb2.x, wb1 = sqdt * nb2.y;
            vA += z0 * wa0 + z1 * wa1 - 0.5f * dt * (z0 * z0 + z1 * z1);
            vB += z2 * wb0 + z3 * wb1 - 0.5f * dt * (z2 * z2 + z3 * z3);
            X[nt][0] += dt * (thv.x - X[nt][0] - z0) + wa0;
            X[nt][1] += dt * (thv.y - X[nt][1] - z1) + wa1;
            X[nt][2] += dt * (thv.x - X[nt][2] - z2) + wb0;
            X[nt][3] += dt * (thv.y - X[nt][3] - z3) + wb1;
        }
        build_xfrags();
    }

    // ---- output ----
    #pragma unroll
    for (int nt = 0; nt < 8; nt++) {
        int col = c * 2 + 8 * nt;
        *(float2*)(out + (size_t)rA * 64 + col) = make_float2(X[nt][0], X[nt][1]);
        *(float2*)(out + (size_t)rB * 64 + col) = make_float2(X[nt][2], X[nt][3]);
    }
    vA += __shfl_down_sync(0xffffffffu, vA, 2, 4);
    vA += __shfl_down_sync(0xffffffffu, vA, 1, 4);
    vB += __shfl_down_sync(0xffffffffu, vB, 2, 4);
    vB += __shfl_down_sync(0xffffffffu, vB, 1, 4);
    if (c == 0) {
        out[(size_t)Nn * 64 + rA] = V0[rA] + vA;
        out[(size_t)Nn * 64 + rB] = V0[rB] + vB;
    }
}

extern "C" void kernel_launch(void* const* d_in, const int* in_sizes, int n_in,
                              void* d_out, int out_size)
{
    (void)in_sizes; (void)n_in; (void)out_size;
    cudaFuncSetAttribute(rollout_mma,
                         cudaFuncAttributeMaxDynamicSharedMemorySize, SMEM_BYTES);

    build_frags<<<64, 256>>>((const float*)d_in[4], (const float*)d_in[6]);
    rollout_mma<<<GRID, THREADS, SMEM_BYTES>>>(
        (const float*)d_in[0], (const float*)d_in[1], (const float*)d_in[2],
        (const float*)d_in[3], (const float*)d_in[4], (const float*)d_in[5],
        (const float*)d_in[6], (const float*)d_in[7], (const float*)d_in[8],
        (const int*)d_in[9],   (float*)d_out);
}

// round 16
// speedup vs baseline: 2.6178x; 1.6438x over previous
#include <cuda_runtime.h>
#include <cuda_fp16.h>
#include <cstdint>
#include <cmath>

// ---------------- problem constants ----------------
#define Nn 8192
#define Mm 50

#define CTA_ROWS 64
#define GRID (Nn / CTA_ROWS)   // 128
#define THREADS 128            // 4 warps, each owns 16 rows

// weight fragment image: per chunk, uint2 entries (plain fp16 weights, 1 term)
//   W1: [ks(6)][nt(8)][lane(32)]  -> 1536 uint2
//   W2: [ks2(4)][nt(8)][lane(32)] -> 1024 uint2, at offset 1536
#define WCH_U2 2560
#define W2_OFF 1536
#define WCH_B  (WCH_U2 * 8)    // 20480 bytes per chunk

// smem layout (bytes)
#define NZ_STRIDE 68                      // floats; 272 B ≡ 0 (mod 16): cp.async-safe
#define NZ_BUF (64 * NZ_STRIDE * 4)       // 17408
#define SM_W   0                          // 2 * 20480 = 40960
#define SM_NZ  40960                      // 2 * 17408 = 34816
#define SM_W0  (SM_NZ + 2 * NZ_BUF)       // 75776
#define SM_B1  (SM_W0 + 2048)
#define SM_B2  (SM_B1 + 2048)
#define SM_TH  (SM_B2 + 256)
#define SMEM_BYTES (SM_TH + 256)          // 80384

__device__ __align__(16) uint2 gWf[8][WCH_U2];

// ---------------- helpers ----------------
__device__ __forceinline__ float ftanh(float x) {
    float y; asm("tanh.approx.f32 %0, %1;" : "=f"(y) : "f"(x)); return y;
}
__device__ __forceinline__ void cp16(uint32_t dst, const void* src) {
    asm volatile("cp.async.cg.shared.global [%0], [%1], 16;" :: "r"(dst), "l"(src));
}
#define CP_COMMIT() asm volatile("cp.async.commit_group;" ::: "memory")
#define CP_WAIT0()  asm volatile("cp.async.wait_group 0;" ::: "memory")

// pack two fp32 (xe = even-k, xo = odd-k) into one f16x2 word, even in low half
__device__ __forceinline__ uint32_t pack_pair(float xe, float xo) {
    uint32_t h;
    asm("cvt.rn.f16x2.f32 %0, %1, %2;" : "=r"(h) : "f"(xo), "f"(xe));
    return h;
}

__device__ __forceinline__ void mma16816(float d[4],
    uint32_t a0, uint32_t a1, uint32_t a2, uint32_t a3, uint2 b) {
    asm volatile(
        "mma.sync.aligned.m16n8k16.row.col.f32.f16.f16.f32 "
        "{%0,%1,%2,%3}, {%4,%5,%6,%7}, {%8,%9}, {%0,%1,%2,%3};"
        : "+f"(d[0]), "+f"(d[1]), "+f"(d[2]), "+f"(d[3])
        : "r"(a0), "r"(a1), "r"(a2), "r"(a3), "r"(b.x), "r"(b.y));
}

// ---------------- setup: prepack weights into B-fragment order, fp16 ----
__global__ void build_frags(const float* __restrict__ W1, const float* __restrict__ W2) {
    int tid = blockIdx.x * blockDim.x + threadIdx.x;
    int stride = gridDim.x * blockDim.x;

    // W1 frags: 8ch x 6ks x 8nt x 32l = 12288 uint2
    for (int i = tid; i < 12288; i += stride) {
        int l  = i & 31;
        int nt = (i >> 5) & 7;
        int ks = (i >> 8) % 6;
        int ch = i / 1536;
        int n  = ch * 64 + nt * 8 + (l >> 2);
        int k0 = ks * 16 + (l & 3) * 2;
        float v[4] = { W1[(size_t)(1 + k0) * 512 + n], W1[(size_t)(2 + k0) * 512 + n],
                       W1[(size_t)(9 + k0) * 512 + n], W1[(size_t)(10 + k0) * 512 + n] };
        uint32_t p[2];
        #pragma unroll
        for (int q = 0; q < 2; q++)
            p[q] = (uint32_t)__half_as_ushort(__float2half(v[2*q]))
                 | ((uint32_t)__half_as_ushort(__float2half(v[2*q + 1])) << 16);
        gWf[ch][(ks * 8 + nt) * 32 + l] = make_uint2(p[0], p[1]);
    }

    // W2 frags: 8ch x 4ks x 8nt x 32l = 8192 uint2
    for (int i = tid; i < 8192; i += stride) {
        int l  = i & 31;
        int nt = (i >> 5) & 7;
        int ks = (i >> 8) % 4;
        int ch = i / 1024;
        int n  = nt * 8 + (l >> 2);
        int k0 = ch * 64 + ks * 16 + (l & 3) * 2;
        float v[4] = { W2[(size_t)k0 * 64 + n],       W2[(size_t)(k0 + 1) * 64 + n],
                       W2[(size_t)(k0 + 8) * 64 + n], W2[(size_t)(k0 + 9) * 64 + n] };
        uint32_t p[2];
        #pragma unroll
        for (int q = 0; q < 2; q++)
            p[q] = (uint32_t)__half_as_ushort(__float2half(v[2*q]))
                 | ((uint32_t)__half_as_ushort(__float2half(v[2*q + 1])) << 16);
        gWf[ch][W2_OFF + (ks * 8 + nt) * 32 + l] = make_uint2(p[0], p[1]);
    }
}

// ---------------- main rollout: fp16 MMA, 1-term weights ----------------
__global__ void __launch_bounds__(THREADS, 1) rollout_mma(
    const float* __restrict__ X0, const float* __restrict__ V0,
    const float* __restrict__ Y,  const float* __restrict__ theta,
    const float* __restrict__ W1, const float* __restrict__ b1,
    const float* __restrict__ W2, const float* __restrict__ b2,
    const float* __restrict__ noise, const int* __restrict__ obs_index,
    float* __restrict__ out)
{
    extern __shared__ __align__(16) unsigned char smem[];
    uint2* sW  = (uint2*)(smem + SM_W);
    float* sNZ = (float*)(smem + SM_NZ);
    float* sW0 = (float*)(smem + SM_W0);
    float* sB1 = (float*)(smem + SM_B1);
    float* sB2 = (float*)(smem + SM_B2);
    float* sTH = (float*)(smem + SM_TH);
    const uint32_t sb = (uint32_t)__cvta_generic_to_shared(smem);

    const int tid = threadIdx.x;
    const int w = tid >> 5, l = tid & 31;
    const int g = l >> 2, c = l & 3;
    const int row0 = blockIdx.x * CTA_ROWS;
    const int rA = row0 + w * 16 + g;       // fragment row (groupID)
    const int rB = rA + 8;                  // fragment row (groupID+8)

    const float dt = 1.0f / (float)Mm;
    const float sqdt = sqrtf(dt);
    const int obs = *obs_index;

    for (int i = tid; i < 512; i += THREADS) { sW0[i] = W1[i]; sB1[i] = b1[i]; }
    if (tid < 64) { sB2[tid] = b2[tid]; sTH[tid] = theta[tid]; }

    // X fp32 state, fragment-distributed: X[j] = {(rA,2c+8j),(rA,+1),(rB,2c+8j),(rB,+1)}
    float X[8][4];
    #pragma unroll
    for (int j = 0; j < 8; j++) {
        int col = c * 2 + 8 * j;
        float2 va = *(const float2*)(X0 + (size_t)rA * 64 + col);
        float2 vb = *(const float2*)(X0 + (size_t)rB * 64 + col);
        X[j][0] = va.x; X[j][1] = va.y; X[j][2] = vb.x; X[j][3] = vb.y;
    }

    // Y A-fragments (static, fp16): GEMM1 k-steps 4,5
    uint32_t Yf[2][4];
    #pragma unroll
    for (int ks = 0; ks < 2; ks++)
        #pragma unroll
        for (int r = 0; r < 2; r++) {
            int yc = ks * 16 + c * 2 + r * 8;
            float2 ya = *(const float2*)(Y + (size_t)rA * 32 + (size_t)obs * 32 + yc);
            float2 yb = *(const float2*)(Y + (size_t)rB * 32 + (size_t)obs * 32 + yc);
            Yf[ks][2*r]     = pack_pair(ya.x, ya.y);
            Yf[ks][2*r + 1] = pack_pair(yb.x, yb.y);
        }

    // X A-fragments (rebuilt per step, fp16)
    uint32_t Xf[4][4];
    auto build_xfrags = [&]() {
        #pragma unroll
        for (int ks = 0; ks < 4; ks++) {
            Xf[ks][0] = pack_pair(X[2*ks][0],     X[2*ks][1]);
            Xf[ks][1] = pack_pair(X[2*ks][2],     X[2*ks][3]);
            Xf[ks][2] = pack_pair(X[2*ks + 1][0], X[2*ks + 1][1]);
            Xf[ks][3] = pack_pair(X[2*ks + 1][2], X[2*ks + 1][3]);
        }
    };
    build_xfrags();

    float vA = 0.0f, vB = 0.0f;

    // prime: chunk 0 weights + step 0 noise
    {
        const uint2* src = gWf[0];
        for (int i = tid; i < WCH_U2 / 2; i += THREADS)
            cp16(sb + SM_W + i * 16, src + i * 2);
        const float* nb = noise + (size_t)row0 * 64;
        for (int i = tid; i < 1024; i += THREADS) {
            int r = i >> 4, jj = i & 15;
            cp16(sb + SM_NZ + r * (NZ_STRIDE * 4) + jj * 16, nb + (size_t)r * 64 + jj * 4);
        }
        CP_COMMIT();
    }

    for (int m = 0; m < Mm; m++) {
        const float s = (float)m * dt;
        float D2[8][4];
        #pragma unroll
        for (int nt = 0; nt < 8; nt++)
            #pragma unroll
            for (int i = 0; i < 4; i++) D2[nt][i] = 0.0f;

        for (int ch = 0; ch < 8; ch++) {
            const int gc = m * 8 + ch;
            CP_WAIT0();
            __syncthreads();              // weights(gc) visible; all warps done with gc-1

            // prefetch next chunk weights (issued AFTER barrier: no buffer race)
            {
                const uint2* src = gWf[(ch + 1) & 7];
                uint32_t dst = sb + SM_W + (((gc + 1) & 1) ? (uint32_t)WCH_B : 0u);
                for (int i = tid; i < WCH_U2 / 2; i += THREADS)
                    cp16(dst + i * 16, src + i * 2);
                CP_COMMIT();
            }
            if (ch == 4 && m + 1 < Mm) {   // stage next step's noise mid-step
                const float* nb = noise + ((size_t)(m + 1) * Nn + (size_t)row0) * 64;
                uint32_t nzd = sb + SM_NZ + (((m + 1) & 1) ? (uint32_t)NZ_BUF : 0u);
                for (int i = tid; i < 1024; i += THREADS) {
                    int r = i >> 4, jj = i & 15;
                    cp16(nzd + r * (NZ_STRIDE * 4) + jj * 16, nb + (size_t)r * 64 + jj * 4);
                }
                CP_COMMIT();
            }

            const uint2* wb = sW + (gc & 1) * WCH_U2;

            // ---- GEMM1: C1[16x64] = [X|Y] @ W1chunk (1 term) ----
            float C1[8][4];
            #pragma unroll
            for (int nt = 0; nt < 8; nt++)
                #pragma unroll
                for (int i = 0; i < 4; i++) C1[nt][i] = 0.0f;

            #pragma unroll
            for (int ks = 0; ks < 6; ks++) {
                uint32_t A0, A1, A2, A3;
                if (ks < 4) { A0 = Xf[ks][0]; A1 = Xf[ks][1]; A2 = Xf[ks][2]; A3 = Xf[ks][3]; }
                else        { A0 = Yf[ks-4][0]; A1 = Yf[ks-4][1]; A2 = Yf[ks-4][2]; A3 = Yf[ks-4][3]; }
                uint2 bh[8];
                #pragma unroll
                for (int nt = 0; nt < 8; nt++) bh[nt] = wb[(ks * 8 + nt) * 32 + l];
                #pragma unroll
                for (int nt = 0; nt < 8; nt++) mma16816(C1[nt], A0, A1, A2, A3, bh[nt]);
            }

            // ---- bias + tanh + fp16 pack -> GEMM2 (C1 frags become A frags) ----
            const int cbase = ch * 64;
            #pragma unroll
            for (int ks2 = 0; ks2 < 4; ks2++) {
                int col0 = cbase + ks2 * 16 + c * 2;
                float2 w0a = *(const float2*)&sW0[col0];
                float2 b1a = *(const float2*)&sB1[col0];
                float2 w0b = *(const float2*)&sW0[col0 + 8];
                float2 b1b = *(const float2*)&sB1[col0 + 8];
                float hb0 = fmaf(s, w0a.x, b1a.x), hb1 = fmaf(s, w0a.y, b1a.y);
                float hb2 = fmaf(s, w0b.x, b1b.x), hb3 = fmaf(s, w0b.y, b1b.y);
                uint32_t a0 = pack_pair(ftanh(C1[2*ks2][0] + hb0), ftanh(C1[2*ks2][1] + hb1));
                uint32_t a1 = pack_pair(ftanh(C1[2*ks2][2] + hb0), ftanh(C1[2*ks2][3] + hb1));
                uint32_t a2 = pack_pair(ftanh(C1[2*ks2+1][0] + hb2), ftanh(C1[2*ks2+1][1] + hb3));
                uint32_t a3 = pack_pair(ftanh(C1[2*ks2+1][2] + hb2), ftanh(C1[2*ks2+1][3] + hb3));

                uint2 bh[8];
                #pragma unroll
                for (int nt = 0; nt < 8; nt++) bh[nt] = wb[W2_OFF + (ks2 * 8 + nt) * 32 + l];
                #pragma unroll
                for (int nt = 0; nt < 8; nt++) mma16816(D2[nt], a0, a1, a2, a3, bh[nt]);
            }
        }

        // ---- step epilogue: Z -> V, X update (all register/fragment local) ----
        const float* nzb = sNZ + (m & 1) * (NZ_BUF / 4) + (w * 16 + g) * NZ_STRIDE + c * 2;
        #pragma unroll
        for (int nt = 0; nt < 8; nt++) {
            int col = c * 2 + 8 * nt;
            float2 b2v = *(const float2*)&sB2[col];
            float2 thv = *(const float2*)&sTH[col];
            float2 na  = *(const float2*)(nzb + 8 * nt);
            float2 nb2 = *(const float2*)(nzb + 8 * NZ_STRIDE + 8 * nt);
            float z0 = D2[nt][0] + b2v.x, z1 = D2[nt][1] + b2v.y;
            float z2 = D2[nt][2] + b2v.x, z3 = D2[nt][3] + b2v.y;
            float wa0 = sqdt * na.x,  wa1 = sqdt * na.y;
            float wb0 = sqdt * nb2.x, wb1 = sqdt * nb2.y;
            vA += z0 * wa0 + z1 * wa1 - 0.5f * dt * (z0 * z0 + z1 * z1);
            vB += z2 * wb0 + z3 * wb1 - 0.5f * dt * (z2 * z2 + z3 * z3);
            X[nt][0] += dt * (thv.x - X[nt][0] - z0) + wa0;
            X[nt][1] += dt * (thv.y - X[nt][1] - z1) + wa1;
            X[nt][2] += dt * (thv.x - X[nt][2] - z2) + wb0;
            X[nt][3] += dt * (thv.y - X[nt][3] - z3) + wb1;
        }
        build_xfrags();
    }

    // ---- output ----
    #pragma unroll
    for (int nt = 0; nt < 8; nt++) {
        int col = c * 2 + 8 * nt;
        *(float2*)(out + (size_t)rA * 64 + col) = make_float2(X[nt][0], X[nt][1]);
        *(float2*)(out + (size_t)rB * 64 + col) = make_float2(X[nt][2], X[nt][3]);
    }
    vA += __shfl_down_sync(0xffffffffu, vA, 2, 4);
    vA += __shfl_down_sync(0xffffffffu, vA, 1, 4);
    vB += __shfl_down_sync(0xffffffffu, vB, 2, 4);
    vB += __shfl_down_sync(0xffffffffu, vB, 1, 4);
    if (c == 0) {
        out[(size_t)Nn * 64 + rA] = V0[rA] + vA;
        out[(size_t)Nn * 64 + rB] = V0[rB] + vB;
    }
}

extern "C" void kernel_launch(void* const* d_in, const int* in_sizes, int n_in,
                              void* d_out, int out_size)
{
    (void)in_sizes; (void)n_in; (void)out_size;
    cudaFuncSetAttribute(rollout_mma,
                         cudaFuncAttributeMaxDynamicSharedMemorySize, SMEM_BYTES);

    build_frags<<<64, 256>>>((const float*)d_in[4], (const float*)d_in[6]);
    rollout_mma<<<GRID, THREADS, SMEM_BYTES>>>(
        (const float*)d_in[0], (const float*)d_in[1], (const float*)d_in[2],
        (const float*)d_in[3], (const float*)d_in[4], (const float*)d_in[5],
        (const float*)d_in[6], (const float*)d_in[7], (const float*)d_in[8],
        (const int*)d_in[9],   (float*)d_out);
}

// round 17
// speedup vs baseline: 3.0804x; 1.1767x over previous
#include <cuda_runtime.h>
#include <cuda_fp16.h>
#include <cstdint>
#include <cmath>

// ---------------- problem constants ----------------
#define Nn 8192
#define Mm 50

#define CTA_ROWS 64
#define GRID (Nn / CTA_ROWS)   // 128
#define THREADS 128            // 4 warps, each owns 16 rows, fully independent

// weight fragment image: per chunk, uint2 entries (fp16 weights)
//   W1: [ks(6)][nt(8)][lane(32)]  -> 1536 uint2
//   W2: [ks2(4)][nt(8)][lane(32)] -> 1024 uint2, at offset 1536
#define WCH_U2 2560
#define W2_OFF 1536
#define WALL_U2 (8 * WCH_U2)   // all 8 chunks resident: 20480 uint2 = 163840 B

// smem layout (bytes)
#define SM_W   0                          // 163840
#define SM_W0  163840                     // 512 f
#define SM_B1  (SM_W0 + 2048)
#define SM_B2  (SM_B1 + 2048)
#define SM_TH  (SM_B2 + 256)
#define SMEM_BYTES (SM_TH + 256)          // 168448

__device__ __align__(16) uint2 gWf[WALL_U2];

// ---------------- helpers ----------------
__device__ __forceinline__ void cp16(uint32_t dst, const void* src) {
    asm volatile("cp.async.cg.shared.global [%0], [%1], 16;" :: "r"(dst), "l"(src));
}
#define CP_COMMIT() asm volatile("cp.async.commit_group;" ::: "memory")
#define CP_WAIT0()  asm volatile("cp.async.wait_group 0;" ::: "memory")

// pack two fp32 (xe = even-k, xo = odd-k) into one f16x2 word, even in low half
__device__ __forceinline__ uint32_t pack_pair(float xe, float xo) {
    uint32_t h;
    asm("cvt.rn.f16x2.f32 %0, %1, %2;" : "=r"(h) : "f"(xo), "f"(xe));
    return h;
}
// packed dual fp16 tanh (one MUFU op for two activations)
__device__ __forceinline__ uint32_t tanh2(uint32_t x) {
    uint32_t y; asm("tanh.approx.f16x2 %0, %1;" : "=r"(y) : "r"(x)); return y;
}

__device__ __forceinline__ void mma16816(float d[4],
    uint32_t a0, uint32_t a1, uint32_t a2, uint32_t a3, uint2 b) {
    asm volatile(
        "mma.sync.aligned.m16n8k16.row.col.f32.f16.f16.f32 "
        "{%0,%1,%2,%3}, {%4,%5,%6,%7}, {%8,%9}, {%0,%1,%2,%3};"
        : "+f"(d[0]), "+f"(d[1]), "+f"(d[2]), "+f"(d[3])
        : "r"(a0), "r"(a1), "r"(a2), "r"(a3), "r"(b.x), "r"(b.y));
}

// ---------------- setup: prepack weights into B-fragment order, fp16 ----
__global__ void build_frags(const float* __restrict__ W1, const float* __restrict__ W2) {
    int tid = blockIdx.x * blockDim.x + threadIdx.x;
    int stride = gridDim.x * blockDim.x;

    // W1 frags: 8ch x 6ks x 8nt x 32l = 12288 uint2
    for (int i = tid; i < 12288; i += stride) {
        int l  = i & 31;
        int nt = (i >> 5) & 7;
        int ks = (i >> 8) % 6;
        int ch = i / 1536;
        int n  = ch * 64 + nt * 8 + (l >> 2);
        int k0 = ks * 16 + (l & 3) * 2;
        float v[4] = { W1[(size_t)(1 + k0) * 512 + n], W1[(size_t)(2 + k0) * 512 + n],
                       W1[(size_t)(9 + k0) * 512 + n], W1[(size_t)(10 + k0) * 512 + n] };
        uint32_t p[2];
        #pragma unroll
        for (int q = 0; q < 2; q++)
            p[q] = (uint32_t)__half_as_ushort(__float2half(v[2*q]))
                 | ((uint32_t)__half_as_ushort(__float2half(v[2*q + 1])) << 16);
        gWf[ch * WCH_U2 + (ks * 8 + nt) * 32 + l] = make_uint2(p[0], p[1]);
    }

    // W2 frags: 8ch x 4ks x 8nt x 32l = 8192 uint2
    for (int i = tid; i < 8192; i += stride) {
        int l  = i & 31;
        int nt = (i >> 5) & 7;
        int ks = (i >> 8) % 4;
        int ch = i / 1024;
        int n  = nt * 8 + (l >> 2);
        int k0 = ch * 64 + ks * 16 + (l & 3) * 2;
        float v[4] = { W2[(size_t)k0 * 64 + n],       W2[(size_t)(k0 + 1) * 64 + n],
                       W2[(size_t)(k0 + 8) * 64 + n], W2[(size_t)(k0 + 9) * 64 + n] };
        uint32_t p[2];
        #pragma unroll
        for (int q = 0; q < 2; q++)
            p[q] = (uint32_t)__half_as_ushort(__float2half(v[2*q]))
                 | ((uint32_t)__half_as_ushort(__float2half(v[2*q + 1])) << 16);
        gWf[ch * WCH_U2 + W2_OFF + (ks * 8 + nt) * 32 + l] = make_uint2(p[0], p[1]);
    }
}

// ---------------- main rollout: all-resident weights, barrier-free loop ----------------
__global__ void __launch_bounds__(THREADS, 1) rollout_mma(
    const float* __restrict__ X0, const float* __restrict__ V0,
    const float* __restrict__ Y,  const float* __restrict__ theta,
    const float* __restrict__ W1, const float* __restrict__ b1,
    const float* __restrict__ W2, const float* __restrict__ b2,
    const float* __restrict__ noise, const int* __restrict__ obs_index,
    float* __restrict__ out)
{
    extern __shared__ __align__(16) unsigned char smem[];
    uint2* sW  = (uint2*)(smem + SM_W);
    float* sW0 = (float*)(smem + SM_W0);
    float* sB1 = (float*)(smem + SM_B1);
    float* sB2 = (float*)(smem + SM_B2);
    float* sTH = (float*)(smem + SM_TH);
    const uint32_t sb = (uint32_t)__cvta_generic_to_shared(smem);

    const int tid = threadIdx.x;
    const int w = tid >> 5, l = tid & 31;
    const int g = l >> 2, c = l & 3;
    const int row0 = blockIdx.x * CTA_ROWS;
    const int rA = row0 + w * 16 + g;       // fragment row (groupID)
    const int rB = rA + 8;                  // fragment row (groupID+8)

    const float dt = 1.0f / (float)Mm;
    const float sqdt = sqrtf(dt);
    const int obs = *obs_index;

    // one-time staging: ALL weights + consts
    for (int i = tid; i < WALL_U2 / 2; i += THREADS)
        cp16(sb + SM_W + i * 16, gWf + i * 2);
    CP_COMMIT();
    for (int i = tid; i < 512; i += THREADS) { sW0[i] = W1[i]; sB1[i] = b1[i]; }
    if (tid < 64) { sB2[tid] = b2[tid]; sTH[tid] = theta[tid]; }

    // X fp32 state, fragment-distributed: X[j] = {(rA,2c+8j),(rA,+1),(rB,2c+8j),(rB,+1)}
    float X[8][4];
    #pragma unroll
    for (int j = 0; j < 8; j++) {
        int col = c * 2 + 8 * j;
        float2 va = *(const float2*)(X0 + (size_t)rA * 64 + col);
        float2 vb = *(const float2*)(X0 + (size_t)rB * 64 + col);
        X[j][0] = va.x; X[j][1] = va.y; X[j][2] = vb.x; X[j][3] = vb.y;
    }

    // Y A-fragments (static, fp16): GEMM1 k-steps 4,5
    uint32_t Yf[2][4];
    #pragma unroll
    for (int ks = 0; ks < 2; ks++)
        #pragma unroll
        for (int r = 0; r < 2; r++) {
            int yc = ks * 16 + c * 2 + r * 8;
            float2 ya = *(const float2*)(Y + (size_t)rA * 32 + (size_t)obs * 32 + yc);
            float2 yb = *(const float2*)(Y + (size_t)rB * 32 + (size_t)obs * 32 + yc);
            Yf[ks][2*r]     = pack_pair(ya.x, ya.y);
            Yf[ks][2*r + 1] = pack_pair(yb.x, yb.y);
        }

    // X A-fragments (rebuilt per step, fp16)
    uint32_t Xf[4][4];
    auto build_xfrags = [&]() {
        #pragma unroll
        for (int ks = 0; ks < 4; ks++) {
            Xf[ks][0] = pack_pair(X[2*ks][0],     X[2*ks][1]);
            Xf[ks][1] = pack_pair(X[2*ks][2],     X[2*ks][3]);
            Xf[ks][2] = pack_pair(X[2*ks + 1][0], X[2*ks + 1][1]);
            Xf[ks][3] = pack_pair(X[2*ks + 1][2], X[2*ks + 1][3]);
        }
    };
    build_xfrags();

    float vA = 0.0f, vB = 0.0f;

    CP_WAIT0();
    __syncthreads();     // the ONLY barrier: weights + consts resident

    for (int m = 0; m < Mm; m++) {
        const float s = (float)m * dt;
        float D2[8][4];
        #pragma unroll
        for (int nt = 0; nt < 8; nt++)
            #pragma unroll
            for (int i = 0; i < 4; i++) D2[nt][i] = 0.0f;

        float2 nA[8], nB[8];

        for (int ch = 0; ch < 8; ch++) {
            const uint2* wb = sW + ch * WCH_U2;

            if (ch == 7) {   // issue this step's noise LDGs; latency hides under MMAs
                #pragma unroll
                for (int nt = 0; nt < 8; nt++) {
                    int col = c * 2 + 8 * nt;
                    nA[nt] = *(const float2*)(noise + ((size_t)m * Nn + rA) * 64 + col);
                    nB[nt] = *(const float2*)(noise + ((size_t)m * Nn + rB) * 64 + col);
                }
            }

            // ---- GEMM1: C1[16x64] = [X|Y] @ W1chunk ----
            float C1[8][4];
            #pragma unroll
            for (int nt = 0; nt < 8; nt++)
                #pragma unroll
                for (int i = 0; i < 4; i++) C1[nt][i] = 0.0f;

            #pragma unroll
            for (int ks = 0; ks < 6; ks++) {
                uint32_t A0, A1, A2, A3;
                if (ks < 4) { A0 = Xf[ks][0]; A1 = Xf[ks][1]; A2 = Xf[ks][2]; A3 = Xf[ks][3]; }
                else        { A0 = Yf[ks-4][0]; A1 = Yf[ks-4][1]; A2 = Yf[ks-4][2]; A3 = Yf[ks-4][3]; }
                uint2 bh[8];
                #pragma unroll
                for (int nt = 0; nt < 8; nt++) bh[nt] = wb[(ks * 8 + nt) * 32 + l];
                #pragma unroll
                for (int nt = 0; nt < 8; nt++) mma16816(C1[nt], A0, A1, A2, A3, bh[nt]);
            }

            // ---- bias + pack + f16x2 tanh -> GEMM2 (C1 frags become A frags) ----
            const int cbase = ch * 64;
            #pragma unroll
            for (int ks2 = 0; ks2 < 4; ks2++) {
                int col0 = cbase + ks2 * 16 + c * 2;
                float2 w0a = *(const float2*)&sW0[col0];
                float2 b1a = *(const float2*)&sB1[col0];
                float2 w0b = *(const float2*)&sW0[col0 + 8];
                float2 b1b = *(const float2*)&sB1[col0 + 8];
                float hb0 = fmaf(s, w0a.x, b1a.x), hb1 = fmaf(s, w0a.y, b1a.y);
                float hb2 = fmaf(s, w0b.x, b1b.x), hb3 = fmaf(s, w0b.y, b1b.y);
                uint32_t a0 = tanh2(pack_pair(C1[2*ks2][0] + hb0,   C1[2*ks2][1] + hb1));
                uint32_t a1 = tanh2(pack_pair(C1[2*ks2][2] + hb0,   C1[2*ks2][3] + hb1));
                uint32_t a2 = tanh2(pack_pair(C1[2*ks2+1][0] + hb2, C1[2*ks2+1][1] + hb3));
                uint32_t a3 = tanh2(pack_pair(C1[2*ks2+1][2] + hb2, C1[2*ks2+1][3] + hb3));

                uint2 bh[8];
                #pragma unroll
                for (int nt = 0; nt < 8; nt++) bh[nt] = wb[W2_OFF + (ks2 * 8 + nt) * 32 + l];
                #pragma unroll
                for (int nt = 0; nt < 8; nt++) mma16816(D2[nt], a0, a1, a2, a3, bh[nt]);
            }
        }

        // ---- step epilogue: Z -> V, X update (all register/fragment local) ----
        #pragma unroll
        for (int nt = 0; nt < 8; nt++) {
            int col = c * 2 + 8 * nt;
            float2 b2v = *(const float2*)&sB2[col];
            float2 thv = *(const float2*)&sTH[col];
            float z0 = D2[nt][0] + b2v.x, z1 = D2[nt][1] + b2v.y;
            float z2 = D2[nt][2] + b2v.x, z3 = D2[nt][3] + b2v.y;
            float wa0 = sqdt * nA[nt].x, wa1 = sqdt * nA[nt].y;
            float wb0 = sqdt * nB[nt].x, wb1 = sqdt * nB[nt].y;
            vA += z0 * wa0 + z1 * wa1 - 0.5f * dt * (z0 * z0 + z1 * z1);
            vB += z2 * wb0 + z3 * wb1 - 0.5f * dt * (z2 * z2 + z3 * z3);
            X[nt][0] += dt * (thv.x - X[nt][0] - z0) + wa0;
            X[nt][1] += dt * (thv.y - X[nt][1] - z1) + wa1;
            X[nt][2] += dt * (thv.x - X[nt][2] - z2) + wb0;
            X[nt][3] += dt * (thv.y - X[nt][3] - z3) + wb1;
        }
        build_xfrags();
    }

    // ---- output ----
    #pragma unroll
    for (int nt = 0; nt < 8; nt++) {
        int col = c * 2 + 8 * nt;
        *(float2*)(out + (size_t)rA * 64 + col) = make_float2(X[nt][0], X[nt][1]);
        *(float2*)(out + (size_t)rB * 64 + col) = make_float2(X[nt][2], X[nt][3]);
    }
    vA += __shfl_down_sync(0xffffffffu, vA, 2, 4);
    vA += __shfl_down_sync(0xffffffffu, vA, 1, 4);
    vB += __shfl_down_sync(0xffffffffu, vB, 2, 4);
    vB += __shfl_down_sync(0xffffffffu, vB, 1, 4);
    if (c == 0) {
        out[(size_t)Nn * 64 + rA] = V0[rA] + vA;
        out[(size_t)Nn * 64 + rB] = V0[rB] + vB;
    }
}

extern "C" void kernel_launch(void* const* d_in, const int* in_sizes, int n_in,
                              void* d_out, int out_size)
{
    (void)in_sizes; (void)n_in; (void)out_size;
    cudaFuncSetAttribute(rollout_mma,
                         cudaFuncAttributeMaxDynamicSharedMemorySize, SMEM_BYTES);

    build_frags<<<64, 256>>>((const float*)d_in[4], (const float*)d_in[6]);
    rollout_mma<<<GRID, THREADS, SMEM_BYTES>>>(
        (const float*)d_in[0], (const float*)d_in[1], (const float*)d_in[2],
        (const float*)d_in[3], (const float*)d_in[4], (const float*)d_in[5],
        (const float*)d_in[6], (const float*)d_in[7], (const float*)d_in[8],
        (const int*)d_in[9],   (float*)d_out);
}